// round 7
// baseline (speedup 1.0000x reference)
#include <cuda_runtime.h>

#define TT 50
#define NN 12
#define MM 4
#define NSC2 16
#define NBATCH 8192
#define BK 64
#define NSYM 78   // 12*13/2 symmetric-packed

// Gains scratch: [step s][entry e (0..51)][batch b]  (52 = 48 K + 4 kff) -- R1 layout
__device__ float g_gains[TT * 52 * NBATCH];

__device__ __forceinline__ int symidx(int i, int j) {
    int a = i < j ? i : j;
    int c = i < j ? j : i;
    return a * NN - (a * (a + 1)) / 2 + c;
}

__global__ void __launch_bounds__(BK) bwd_kernel(
    const float* __restrict__ Qg, const float* __restrict__ pg,
    const float* __restrict__ Ag, const float* __restrict__ Bg)
{
    __shared__ float sm[192 + 2 * NSYM * BK];
    const int tid = threadIdx.x;
    const int b = blockIdx.x * BK + tid;

    for (int e = tid; e < 192; e += BK) sm[e] = (e < 144) ? Ag[e] : Bg[e - 144];
    __syncthreads();
    const float* sA = sm;          // A[i*12+j]
    const float* sB = sm + 144;    // B[i*4+m]
    float* Vbuf0 = sm + 192 + tid;             // element e at Vbuf0[e*BK]
    float* Vbuf1 = Vbuf0 + NSYM * BK;

    // Per-batch cost weights
    float Qx[NN], Qu[MM], px[NN], pu[MM];
    {
        const float4* q4 = reinterpret_cast<const float4*>(Qg + b * NSC2);
        float4 a0 = q4[0], a1 = q4[1], a2 = q4[2], a3 = q4[3];
        Qx[0]=a0.x; Qx[1]=a0.y; Qx[2]=a0.z; Qx[3]=a0.w;
        Qx[4]=a1.x; Qx[5]=a1.y; Qx[6]=a1.z; Qx[7]=a1.w;
        Qx[8]=a2.x; Qx[9]=a2.y; Qx[10]=a2.z; Qx[11]=a2.w;
        Qu[0]=a3.x; Qu[1]=a3.y; Qu[2]=a3.z; Qu[3]=a3.w;
        const float4* p4 = reinterpret_cast<const float4*>(pg + b * NSC2);
        float4 b0 = p4[0], b1 = p4[1], b2 = p4[2], b3 = p4[3];
        px[0]=b0.x; px[1]=b0.y; px[2]=b0.z; px[3]=b0.w;
        px[4]=b1.x; px[5]=b1.y; px[6]=b1.z; px[7]=b1.w;
        px[8]=b2.x; px[9]=b2.y; px[10]=b2.z; px[11]=b2.w;
        pu[0]=b3.x; pu[1]=b3.y; pu[2]=b3.z; pu[3]=b3.w;
    }

    // V = 0, v = 0
    #pragma unroll
    for (int e = 0; e < NSYM; e++) Vbuf0[e * BK] = 0.0f;
    float v[NN];
    #pragma unroll
    for (int i = 0; i < NN; i++) v[i] = 0.0f;

    #pragma unroll 1
    for (int s = 0; s < TT; s++) {
        float* Vr = (s & 1) ? Vbuf1 : Vbuf0;
        float* Vw = (s & 1) ? Vbuf0 : Vbuf1;

        // ---- VB = V * B  (12x4) ----
        float VB[NN][MM];
        #pragma unroll
        for (int i = 0; i < NN; i++)
            #pragma unroll
            for (int m = 0; m < MM; m++) VB[i][m] = 0.0f;
        #pragma unroll
        for (int j = 0; j < NN; j++) {
            float bj0 = sB[j*MM+0], bj1 = sB[j*MM+1], bj2 = sB[j*MM+2], bj3 = sB[j*MM+3];
            #pragma unroll
            for (int i = 0; i < NN; i++) {
                float vij = Vr[symidx(i, j) * BK];
                VB[i][0] += vij * bj0;
                VB[i][1] += vij * bj1;
                VB[i][2] += vij * bj2;
                VB[i][3] += vij * bj3;
            }
        }

        // ---- Quu = diag(Qu) + B^T VB ; qu = pu + B^T v ----
        float Quu[MM][MM];
        float qu[MM];
        #pragma unroll
        for (int m = 0; m < MM; m++) {
            qu[m] = pu[m];
            #pragma unroll
            for (int n2 = m; n2 < MM; n2++) Quu[m][n2] = (m == n2) ? Qu[m] : 0.0f;
        }
        #pragma unroll
        for (int i = 0; i < NN; i++) {
            float bi0 = sB[i*MM+0], bi1 = sB[i*MM+1], bi2 = sB[i*MM+2], bi3 = sB[i*MM+3];
            qu[0] += bi0 * v[i]; qu[1] += bi1 * v[i];
            qu[2] += bi2 * v[i]; qu[3] += bi3 * v[i];
            Quu[0][0] += bi0 * VB[i][0]; Quu[0][1] += bi0 * VB[i][1];
            Quu[0][2] += bi0 * VB[i][2]; Quu[0][3] += bi0 * VB[i][3];
            Quu[1][1] += bi1 * VB[i][1]; Quu[1][2] += bi1 * VB[i][2];
            Quu[1][3] += bi1 * VB[i][3];
            Quu[2][2] += bi2 * VB[i][2]; Quu[2][3] += bi2 * VB[i][3];
            Quu[3][3] += bi3 * VB[i][3];
        }

        // ---- Mx = A^T VB  (Qxu, 12x4) ----
        float Mx[NN][MM];
        #pragma unroll
        for (int n = 0; n < NN; n++)
            #pragma unroll
            for (int m = 0; m < MM; m++) Mx[n][m] = 0.0f;
        #pragma unroll
        for (int i = 0; i < NN; i++) {
            #pragma unroll
            for (int n = 0; n < NN; n++) {
                float ain = sA[i*NN+n];
                Mx[n][0] += ain * VB[i][0];
                Mx[n][1] += ain * VB[i][1];
                Mx[n][2] += ain * VB[i][2];
                Mx[n][3] += ain * VB[i][3];
            }
        }

        // ---- Cholesky of Quu (SPD), upper-triangle inputs ----
        float l00 = sqrtf(Quu[0][0]);           float i00 = 1.0f / l00;
        float L10 = Quu[0][1] * i00;
        float L20 = Quu[0][2] * i00;
        float L30 = Quu[0][3] * i00;
        float l11 = sqrtf(Quu[1][1] - L10*L10); float i11 = 1.0f / l11;
        float L21 = (Quu[1][2] - L20*L10) * i11;
        float L31 = (Quu[1][3] - L30*L10) * i11;
        float l22 = sqrtf(Quu[2][2] - L20*L20 - L21*L21); float i22 = 1.0f / l22;
        float L32 = (Quu[2][3] - L30*L20 - L31*L21) * i22;
        float l33 = sqrtf(Quu[3][3] - L30*L30 - L31*L31 - L32*L32); float i33 = 1.0f / l33;

        // ---- Zt[n][m] = (L^{-1} Qux[:,n])_m   (forward substitution per column) ----
        float Zt[NN][MM];
        #pragma unroll
        for (int n = 0; n < NN; n++) {
            float y0 = Mx[n][0] * i00;
            float y1 = (Mx[n][1] - L10*y0) * i11;
            float y2 = (Mx[n][2] - L20*y0 - L21*y1) * i22;
            float y3 = (Mx[n][3] - L30*y0 - L31*y1 - L32*y2) * i33;
            Zt[n][0] = y0; Zt[n][1] = y1; Zt[n][2] = y2; Zt[n][3] = y3;
        }
        // zq = L^{-1} qu
        float zq0 = qu[0] * i00;
        float zq1 = (qu[1] - L10*zq0) * i11;
        float zq2 = (qu[2] - L20*zq0 - L21*zq1) * i22;
        float zq3 = (qu[3] - L30*zq0 - L31*zq1 - L32*zq2) * i33;

        // ---- gains (store only; not needed for the recursion) ----
        {
            const int base = (s * 52) * NBATCH + b;
            // K[:,n] = -L^{-T} Zt[n]
            #pragma unroll
            for (int n = 0; n < NN; n++) {
                float w3 = Zt[n][3] * i33;
                float w2 = (Zt[n][2] - L32*w3) * i22;
                float w1 = (Zt[n][1] - L21*w2 - L31*w3) * i11;
                float w0 = (Zt[n][0] - L10*w1 - L20*w2 - L30*w3) * i00;
                g_gains[base + (0*NN + n) * NBATCH] = -w0;
                g_gains[base + (1*NN + n) * NBATCH] = -w1;
                g_gains[base + (2*NN + n) * NBATCH] = -w2;
                g_gains[base + (3*NN + n) * NBATCH] = -w3;
            }
            // kff = -L^{-T} zq
            float w3 = zq3 * i33;
            float w2 = (zq2 - L32*w3) * i22;
            float w1 = (zq1 - L21*w2 - L31*w3) * i11;
            float w0 = (zq0 - L10*w1 - L20*w2 - L30*w3) * i00;
            g_gains[base + (48 + 0) * NBATCH] = -w0;
            g_gains[base + (48 + 1) * NBATCH] = -w1;
            g_gains[base + (48 + 2) * NBATCH] = -w2;
            g_gains[base + (48 + 3) * NBATCH] = -w3;
        }

        // ---- Vn = diag(Qx) + A^T V A - Zt Zt^T  (upper tri, blocked like R1) ----
        #pragma unroll
        for (int blk = 0; blk < 3; blk++) {
            const int c0 = blk * 4;
            // P[:,cc] = V * A[:, c0+cc]
            float P[NN][4];
            #pragma unroll
            for (int i = 0; i < NN; i++)
                #pragma unroll
                for (int cc = 0; cc < 4; cc++) P[i][cc] = 0.0f;
            #pragma unroll
            for (int j = 0; j < NN; j++) {
                float a0 = sA[j*NN + c0+0], a1 = sA[j*NN + c0+1];
                float a2 = sA[j*NN + c0+2], a3 = sA[j*NN + c0+3];
                #pragma unroll
                for (int i = 0; i < NN; i++) {
                    float vij = Vr[symidx(i, j) * BK];
                    P[i][0] += vij * a0;
                    P[i][1] += vij * a1;
                    P[i][2] += vij * a2;
                    P[i][3] += vij * a3;
                }
            }
            #pragma unroll
            for (int r = 0; r < NN; r++) {
                if (r > c0 + 3) continue;   // folds at compile time
                float ar[NN];
                #pragma unroll
                for (int i = 0; i < NN; i++) ar[i] = sA[i*NN + r];
                #pragma unroll
                for (int cc = 0; cc < 4; cc++) {
                    const int c = c0 + cc;
                    if (r <= c) {
                        float val = (r == c) ? Qx[r] : 0.0f;
                        #pragma unroll
                        for (int i = 0; i < NN; i++) val += ar[i] * P[i][cc];
                        #pragma unroll
                        for (int m = 0; m < MM; m++) val -= Zt[r][m] * Zt[c][m];
                        Vw[symidx(r, c) * BK] = val;
                    }
                }
            }
        }

        // ---- vn = px + A^T v - Zt zq ----
        float vn[NN];
        #pragma unroll
        for (int n = 0; n < NN; n++)
            vn[n] = px[n] - (Zt[n][0]*zq0 + Zt[n][1]*zq1 + Zt[n][2]*zq2 + Zt[n][3]*zq3);
        #pragma unroll
        for (int i = 0; i < NN; i++) {
            float vi = v[i];
            #pragma unroll
            for (int n = 0; n < NN; n++) vn[n] += sA[i*NN + n] * vi;
        }
        #pragma unroll
        for (int n = 0; n < NN; n++) v[n] = vn[n];
    }
}

__global__ void __launch_bounds__(BK) fwd_kernel(
    const float* __restrict__ x_init, const float* __restrict__ Ag,
    const float* __restrict__ Bg, float* __restrict__ out)
{
    __shared__ float sm[192];
    const int tid = threadIdx.x;
    const int b = blockIdx.x * BK + tid;
    for (int e = tid; e < 192; e += BK) sm[e] = (e < 144) ? Ag[e] : Bg[e - 144];
    __syncthreads();
    const float* sA = sm;
    const float* sB = sm + 144;

    float x[NN];
    #pragma unroll
    for (int i = 0; i < NN; i++) x[i] = x_init[b * NN + i];

    #pragma unroll 1
    for (int t = 0; t < TT; t++) {
        const int s = TT - 1 - t;           // gains stored in backward order
        const int base = (s * 52) * NBATCH + b;
        float K[MM][NN], kff[MM];
        #pragma unroll
        for (int m = 0; m < MM; m++)
            #pragma unroll
            for (int n = 0; n < NN; n++)
                K[m][n] = g_gains[base + (m*NN + n) * NBATCH];
        #pragma unroll
        for (int m = 0; m < MM; m++) kff[m] = g_gains[base + (48 + m) * NBATCH];

        float u[MM];
        #pragma unroll
        for (int m = 0; m < MM; m++) {
            float acc = kff[m];
            #pragma unroll
            for (int n = 0; n < NN; n++) acc += K[m][n] * x[n];
            u[m] = acc;
        }
        float xn[NN];
        #pragma unroll
        for (int i = 0; i < NN; i++) {
            float acc = 0.0f;
            #pragma unroll
            for (int j = 0; j < NN; j++) acc += sA[i*NN + j] * x[j];
            #pragma unroll
            for (int m = 0; m < MM; m++) acc += sB[i*MM + m] * u[m];
            xn[i] = acc;
        }
        #pragma unroll
        for (int i = 0; i < NN; i++) x[i] = xn[i];

        float4 uo;
        uo.x = u[0]; uo.y = u[1]; uo.z = u[2]; uo.w = u[3];
        *reinterpret_cast<float4*>(out + ((size_t)t * NBATCH + b) * MM) = uo;
    }
}

extern "C" void kernel_launch(void* const* d_in, const int* in_sizes, int n_in,
                              void* d_out, int out_size) {
    const float* x_init = (const float*)d_in[0];
    const float* Q      = (const float*)d_in[1];
    const float* p      = (const float*)d_in[2];
    const float* A      = (const float*)d_in[3];
    const float* B      = (const float*)d_in[4];
    float* out = (float*)d_out;

    bwd_kernel<<<NBATCH / BK, BK>>>(Q, p, A, B);
    fwd_kernel<<<NBATCH / BK, BK>>>(x_init, A, B, out);
}

// round 10
// speedup vs baseline: 1.2573x; 1.2573x over previous
#include <cuda_runtime.h>

#define TT 50
#define NN 12
#define MM 4
#define NBATCH 8192
#define BK 32             // bwd block: 1 warp, grid 256 -> all 148 SMs
#define BKF 64            // fwd block
typedef unsigned long long ull;

// Gains scratch: [step s][entry e (0..51)][batch b]  (52 = 48 K + 4 kff) -- verified layout
__device__ float g_gains[TT * 52 * NBATCH];

#define FMA2(d, a, b, c) asm("fma.rn.f32x2 %0, %1, %2, %3;" : "=l"(d) : "l"(a), "l"(b), "l"(c))
#define MUL2(d, a, b)    asm("mul.rn.f32x2 %0, %1, %2;"     : "=l"(d) : "l"(a), "l"(b))
#define PACKD(d, x)      asm("mov.b64 %0, {%1, %2};" : "=l"(d) : "f"(x), "f"(x))
#define PACK2(d, lo, hi) asm("mov.b64 %0, {%1, %2};" : "=l"(d) : "f"(lo), "f"(hi))
#define UNPK2(lo, hi, s) asm("mov.b64 {%0, %1}, %2;" : "=f"(lo), "=f"(hi) : "l"(s))

__global__ void __launch_bounds__(BK) bwd_kernel(
    const float* __restrict__ Qg, const float* __restrict__ pg,
    const float* __restrict__ Ag, const float* __restrict__ Bg)
{
    __shared__ __align__(16) float sA[144];   // A[i*12+j]
    __shared__ __align__(16) float sB[48];    // B[i*4+m]
    __shared__ ull sBp[24];                   // [jp*4+m]  = (B[2jp][m], B[2jp+1][m])
    __shared__ ull sAcp[72];                  // [blk*24+jp*4+cc] = (A[2jp][c0+cc], A[2jp+1][c0+cc])
    __shared__ ull sV0[72 * BK];              // V[i][2jp..2jp+1] of thread t at (i*6+jp)*BK+t
    __shared__ ull sV1[72 * BK];

    const int tid = threadIdx.x;
    const int b = blockIdx.x * BK + tid;

    for (int e = tid; e < 192; e += BK) {
        if (e < 144) sA[e] = Ag[e]; else sB[e - 144] = Bg[e - 144];
    }
    // packed B column-pairs: float half h of slot (jp*4+m)
    for (int e = tid; e < 48; e += BK) {
        int h = e & 1, r = e >> 1, m = r & 3, jp = r >> 2;
        reinterpret_cast<float*>(sBp)[2 * (jp * 4 + m) + h] = Bg[(2 * jp + h) * 4 + m];
    }
    // packed A column-pairs per 4-col block
    for (int e = tid; e < 144; e += BK) {
        int h = e & 1, r = e >> 1, cc = r & 3, jp = (r >> 2) % 6, blk = r / 24;
        reinterpret_cast<float*>(sAcp)[2 * (blk * 24 + jp * 4 + cc) + h] =
            Ag[(2 * jp + h) * 12 + blk * 4 + cc];
    }
    __syncthreads();

    // Per-batch cost weights
    float Qx[NN], Qu[MM], px[NN], pu[MM];
    #pragma unroll
    for (int i = 0; i < NN; i++) { Qx[i] = Qg[b * 16 + i]; px[i] = pg[b * 16 + i]; }
    #pragma unroll
    for (int m = 0; m < MM; m++) { Qu[m] = Qg[b * 16 + 12 + m]; pu[m] = pg[b * 16 + 12 + m]; }

    // V = 0 (own slots, private per thread), v = 0
    #pragma unroll
    for (int e = 0; e < 72; e++) sV0[e * BK + tid] = 0ull;
    float v[NN];
    #pragma unroll
    for (int i = 0; i < NN; i++) v[i] = 0.0f;

    #pragma unroll 1
    for (int s = 0; s < TT; s++) {
        ull* Vr = (s & 1) ? sV1 : sV0;
        ull* Vw = (s & 1) ? sV0 : sV1;

        // ---- VB = V * B : packed reduction over j-pairs ----
        float VB[NN][MM];
        {
            ull bpu[6][4];
            #pragma unroll
            for (int jp = 0; jp < 6; jp++)
                #pragma unroll
                for (int m = 0; m < MM; m++) bpu[jp][m] = sBp[jp * 4 + m];
            #pragma unroll
            for (int i = 0; i < NN; i++) {
                ull vp[6];
                #pragma unroll
                for (int jp = 0; jp < 6; jp++) vp[jp] = Vr[(i * 6 + jp) * BK + tid];
                #pragma unroll
                for (int m = 0; m < MM; m++) {
                    ull acc;
                    MUL2(acc, vp[0], bpu[0][m]);
                    #pragma unroll
                    for (int jp = 1; jp < 6; jp++) FMA2(acc, vp[jp], bpu[jp][m], acc);
                    float lo, hi; UNPK2(lo, hi, acc);
                    VB[i][m] = lo + hi;
                }
            }
        }

        // ---- Quu = diag(Qu) + B^T VB ; qu = pu + B^T v  (verified scalar) ----
        float Quu[MM][MM];
        float qu[MM];
        #pragma unroll
        for (int m = 0; m < MM; m++) {
            qu[m] = pu[m];
            #pragma unroll
            for (int n2 = m; n2 < MM; n2++) Quu[m][n2] = (m == n2) ? Qu[m] : 0.0f;
        }
        #pragma unroll
        for (int i = 0; i < NN; i++) {
            float bi0 = sB[i*MM+0], bi1 = sB[i*MM+1], bi2 = sB[i*MM+2], bi3 = sB[i*MM+3];
            qu[0] += bi0 * v[i]; qu[1] += bi1 * v[i];
            qu[2] += bi2 * v[i]; qu[3] += bi3 * v[i];
            Quu[0][0] += bi0 * VB[i][0]; Quu[0][1] += bi0 * VB[i][1];
            Quu[0][2] += bi0 * VB[i][2]; Quu[0][3] += bi0 * VB[i][3];
            Quu[1][1] += bi1 * VB[i][1]; Quu[1][2] += bi1 * VB[i][2];
            Quu[1][3] += bi1 * VB[i][3];
            Quu[2][2] += bi2 * VB[i][2]; Quu[2][3] += bi2 * VB[i][3];
            Quu[3][3] += bi3 * VB[i][3];
        }

        // ---- Mx = A^T VB : packed along n (A-row pairs via LDS.64, dup'd VB) ----
        float Mx[NN][MM];
        {
            ull Mxp[6][4];
            #pragma unroll
            for (int np = 0; np < 6; np++)
                #pragma unroll
                for (int m = 0; m < MM; m++) Mxp[np][m] = 0ull;
            #pragma unroll
            for (int i = 0; i < NN; i++) {
                ull vbd[4];
                #pragma unroll
                for (int m = 0; m < MM; m++) PACKD(vbd[m], VB[i][m]);
                #pragma unroll
                for (int np = 0; np < 6; np++) {
                    ull ap = *reinterpret_cast<const ull*>(sA + i * 12 + 2 * np);
                    #pragma unroll
                    for (int m = 0; m < MM; m++) FMA2(Mxp[np][m], ap, vbd[m], Mxp[np][m]);
                }
            }
            #pragma unroll
            for (int np = 0; np < 6; np++)
                #pragma unroll
                for (int m = 0; m < MM; m++) {
                    float lo, hi; UNPK2(lo, hi, Mxp[np][m]);
                    Mx[2*np][m] = lo; Mx[2*np+1][m] = hi;
                }
        }

        // ---- Cholesky of Quu (verified scalar) ----
        float l00 = sqrtf(Quu[0][0]);           float i00 = 1.0f / l00;
        float L10 = Quu[0][1] * i00;
        float L20 = Quu[0][2] * i00;
        float L30 = Quu[0][3] * i00;
        float l11 = sqrtf(Quu[1][1] - L10*L10); float i11 = 1.0f / l11;
        float L21 = (Quu[1][2] - L20*L10) * i11;
        float L31 = (Quu[1][3] - L30*L10) * i11;
        float l22 = sqrtf(Quu[2][2] - L20*L20 - L21*L21); float i22 = 1.0f / l22;
        float L32 = (Quu[2][3] - L30*L20 - L31*L21) * i22;
        float l33 = sqrtf(Quu[3][3] - L30*L30 - L31*L31 - L32*L32); float i33 = 1.0f / l33;

        // ---- Zt[n][m] = (L^{-1} Qux[:,n])_m ----
        float Zt[NN][MM];
        #pragma unroll
        for (int n = 0; n < NN; n++) {
            float y0 = Mx[n][0] * i00;
            float y1 = (Mx[n][1] - L10*y0) * i11;
            float y2 = (Mx[n][2] - L20*y0 - L21*y1) * i22;
            float y3 = (Mx[n][3] - L30*y0 - L31*y1 - L32*y2) * i33;
            Zt[n][0] = y0; Zt[n][1] = y1; Zt[n][2] = y2; Zt[n][3] = y3;
        }
        float zq0 = qu[0] * i00;
        float zq1 = (qu[1] - L10*zq0) * i11;
        float zq2 = (qu[2] - L20*zq0 - L21*zq1) * i22;
        float zq3 = (qu[3] - L30*zq0 - L31*zq1 - L32*zq2) * i33;

        // ---- gains (verified scalar + layout) ----
        {
            const int base = (s * 52) * NBATCH + b;
            #pragma unroll
            for (int n = 0; n < NN; n++) {
                float w3 = Zt[n][3] * i33;
                float w2 = (Zt[n][2] - L32*w3) * i22;
                float w1 = (Zt[n][1] - L21*w2 - L31*w3) * i11;
                float w0 = (Zt[n][0] - L10*w1 - L20*w2 - L30*w3) * i00;
                g_gains[base + (0*NN + n) * NBATCH] = -w0;
                g_gains[base + (1*NN + n) * NBATCH] = -w1;
                g_gains[base + (2*NN + n) * NBATCH] = -w2;
                g_gains[base + (3*NN + n) * NBATCH] = -w3;
            }
            float w3 = zq3 * i33;
            float w2 = (zq2 - L32*w3) * i22;
            float w1 = (zq1 - L21*w2 - L31*w3) * i11;
            float w0 = (zq0 - L10*w1 - L20*w2 - L30*w3) * i00;
            g_gains[base + (48 + 0) * NBATCH] = -w0;
            g_gains[base + (48 + 1) * NBATCH] = -w1;
            g_gains[base + (48 + 2) * NBATCH] = -w2;
            g_gains[base + (48 + 3) * NBATCH] = -w3;
        }

        // ---- vn = px + A^T v - Zt zq : init scalar, A^T v packed along n ----
        {
            float vn[NN];
            #pragma unroll
            for (int n = 0; n < NN; n++)
                vn[n] = px[n] - (Zt[n][0]*zq0 + Zt[n][1]*zq1 + Zt[n][2]*zq2 + Zt[n][3]*zq3);
            ull vnp[6];
            #pragma unroll
            for (int np = 0; np < 6; np++) PACK2(vnp[np], vn[2*np], vn[2*np+1]);
            #pragma unroll
            for (int i = 0; i < NN; i++) {
                ull vd; PACKD(vd, v[i]);
                #pragma unroll
                for (int np = 0; np < 6; np++) {
                    ull ap = *reinterpret_cast<const ull*>(sA + i * 12 + 2 * np);
                    FMA2(vnp[np], ap, vd, vnp[np]);
                }
            }
            #pragma unroll
            for (int np = 0; np < 6; np++) {
                float lo, hi; UNPK2(lo, hi, vnp[np]);
                v[2*np] = lo; v[2*np+1] = hi;
            }
        }

        // ---- Vn = diag(Qx) + A^T V A - Zt Zt^T  (upper tri, blocked; P packed) ----
        float* fVw = reinterpret_cast<float*>(Vw);
        #pragma unroll
        for (int blk = 0; blk < 3; blk++) {
            const int c0 = blk * 4;
            // P[:,cc] = V * A[:, c0+cc] : packed reduction over j-pairs
            float P[NN][4];
            {
                ull apu[6][4];
                #pragma unroll
                for (int jp = 0; jp < 6; jp++)
                    #pragma unroll
                    for (int cc = 0; cc < 4; cc++) apu[jp][cc] = sAcp[blk * 24 + jp * 4 + cc];
                #pragma unroll
                for (int i = 0; i < NN; i++) {
                    ull vp[6];
                    #pragma unroll
                    for (int jp = 0; jp < 6; jp++) vp[jp] = Vr[(i * 6 + jp) * BK + tid];
                    #pragma unroll
                    for (int cc = 0; cc < 4; cc++) {
                        ull acc;
                        MUL2(acc, vp[0], apu[0][cc]);
                        #pragma unroll
                        for (int jp = 1; jp < 6; jp++) FMA2(acc, vp[jp], apu[jp][cc], acc);
                        float lo, hi; UNPK2(lo, hi, acc);
                        P[i][cc] = lo + hi;
                    }
                }
            }
            // rows r <= c: val = Qx-diag + sum_i A[i][r] P[i][cc] - Zt[r]·Zt[c]
            #pragma unroll
            for (int r = 0; r < NN; r++) {
                if (r > c0 + 3) continue;   // folds at compile time
                float ar[NN];
                #pragma unroll
                for (int i = 0; i < NN; i++) ar[i] = sA[i*NN + r];
                #pragma unroll
                for (int cc = 0; cc < 4; cc++) {
                    const int c = c0 + cc;
                    if (r <= c) {
                        float val = (r == c) ? Qx[r] : 0.0f;
                        #pragma unroll
                        for (int i = 0; i < NN; i++) val += ar[i] * P[i][cc];
                        #pragma unroll
                        for (int m = 0; m < MM; m++) val -= Zt[r][m] * Zt[c][m];
                        // write (r,c) and mirror (c,r) into pair-layout V
                        fVw[2 * ((r * 6 + (c >> 1)) * BK + tid) + (c & 1)] = val;
                        if (r != c)
                            fVw[2 * ((c * 6 + (r >> 1)) * BK + tid) + (r & 1)] = val;
                    }
                }
            }
        }
        // per-thread private V: no synchronization needed
    }
}

// ---------- forward pass: verified kernel, verbatim ----------
__global__ void __launch_bounds__(BKF) fwd_kernel(
    const float* __restrict__ x_init, const float* __restrict__ Ag,
    const float* __restrict__ Bg, float* __restrict__ out)
{
    __shared__ float sm[192];
    const int tid = threadIdx.x;
    const int b = blockIdx.x * BKF + tid;
    for (int e = tid; e < 192; e += BKF) sm[e] = (e < 144) ? Ag[e] : Bg[e - 144];
    __syncthreads();
    const float* sA = sm;
    const float* sB = sm + 144;

    float x[NN];
    #pragma unroll
    for (int i = 0; i < NN; i++) x[i] = x_init[b * NN + i];

    #pragma unroll 1
    for (int t = 0; t < TT; t++) {
        const int s = TT - 1 - t;           // gains stored in backward order
        const int base = (s * 52) * NBATCH + b;
        float K[MM][NN], kff[MM];
        #pragma unroll
        for (int m = 0; m < MM; m++)
            #pragma unroll
            for (int n = 0; n < NN; n++)
                K[m][n] = g_gains[base + (m*NN + n) * NBATCH];
        #pragma unroll
        for (int m = 0; m < MM; m++) kff[m] = g_gains[base + (48 + m) * NBATCH];

        float u[MM];
        #pragma unroll
        for (int m = 0; m < MM; m++) {
            float acc = kff[m];
            #pragma unroll
            for (int n = 0; n < NN; n++) acc += K[m][n] * x[n];
            u[m] = acc;
        }
        float xn[NN];
        #pragma unroll
        for (int i = 0; i < NN; i++) {
            float acc = 0.0f;
            #pragma unroll
            for (int j = 0; j < NN; j++) acc += sA[i*NN + j] * x[j];
            #pragma unroll
            for (int m = 0; m < MM; m++) acc += sB[i*MM + m] * u[m];
            xn[i] = acc;
        }
        #pragma unroll
        for (int i = 0; i < NN; i++) x[i] = xn[i];

        float4 uo;
        uo.x = u[0]; uo.y = u[1]; uo.z = u[2]; uo.w = u[3];
        *reinterpret_cast<float4*>(out + ((size_t)t * NBATCH + b) * MM) = uo;
    }
}

extern "C" void kernel_launch(void* const* d_in, const int* in_sizes, int n_in,
                              void* d_out, int out_size) {
    const float* x_init = (const float*)d_in[0];
    const float* Q      = (const float*)d_in[1];
    const float* p      = (const float*)d_in[2];
    const float* A      = (const float*)d_in[3];
    const float* B      = (const float*)d_in[4];
    float* out = (float*)d_out;

    bwd_kernel<<<NBATCH / BK, BK>>>(Q, p, A, B);           // 256 blocks x 32 thr
    fwd_kernel<<<NBATCH / BKF, BKF>>>(x_init, A, B, out);  // 128 blocks x 64 thr
}

// round 12
// speedup vs baseline: 1.2839x; 1.0211x over previous
#include <cuda_runtime.h>

#define TT 50
#define NN 12
#define MM 4
#define NSC2 16
#define NBATCH 8192
#define BK 64
#define NSYM 78   // 12*13/2 symmetric-packed
#define BKF 128   // fwd block: 32 quads

// Gains scratch: [step s][entry e (0..51)][batch b]  (52 = 48 K + 4 kff)
__device__ float g_gains[TT * 52 * NBATCH];

__device__ __forceinline__ int symidx(int i, int j) {
    int a = i < j ? i : j;
    int c = i < j ? j : i;
    return a * NN - (a * (a + 1)) / 2 + c;
}

__global__ void __launch_bounds__(BK) bwd_kernel(
    const float* __restrict__ Qg, const float* __restrict__ pg,
    const float* __restrict__ Ag, const float* __restrict__ Bg)
{
    __shared__ float sm[192 + 2 * NSYM * BK];
    const int tid = threadIdx.x;
    const int b = blockIdx.x * BK + tid;

    for (int e = tid; e < 192; e += BK) sm[e] = (e < 144) ? Ag[e] : Bg[e - 144];
    __syncthreads();
    const float* sA = sm;          // A[i*12+j]
    const float* sB = sm + 144;    // B[i*4+m]
    float* Vbuf0 = sm + 192 + tid;             // element e at Vbuf0[e*BK]
    float* Vbuf1 = Vbuf0 + NSYM * BK;

    // Per-batch cost weights
    float Qx[NN], Qu[MM], px[NN], pu[MM];
    {
        const float4* q4 = reinterpret_cast<const float4*>(Qg + b * NSC2);
        float4 a0 = q4[0], a1 = q4[1], a2 = q4[2], a3 = q4[3];
        Qx[0]=a0.x; Qx[1]=a0.y; Qx[2]=a0.z; Qx[3]=a0.w;
        Qx[4]=a1.x; Qx[5]=a1.y; Qx[6]=a1.z; Qx[7]=a1.w;
        Qx[8]=a2.x; Qx[9]=a2.y; Qx[10]=a2.z; Qx[11]=a2.w;
        Qu[0]=a3.x; Qu[1]=a3.y; Qu[2]=a3.z; Qu[3]=a3.w;
        const float4* p4 = reinterpret_cast<const float4*>(pg + b * NSC2);
        float4 b0 = p4[0], b1 = p4[1], b2 = p4[2], b3 = p4[3];
        px[0]=b0.x; px[1]=b0.y; px[2]=b0.z; px[3]=b0.w;
        px[4]=b1.x; px[5]=b1.y; px[6]=b1.z; px[7]=b1.w;
        px[8]=b2.x; px[9]=b2.y; px[10]=b2.z; px[11]=b2.w;
        pu[0]=b3.x; pu[1]=b3.y; pu[2]=b3.z; pu[3]=b3.w;
    }

    // V = 0, v = 0
    #pragma unroll
    for (int e = 0; e < NSYM; e++) Vbuf0[e * BK] = 0.0f;
    float v[NN];
    #pragma unroll
    for (int i = 0; i < NN; i++) v[i] = 0.0f;

    #pragma unroll 1
    for (int s = 0; s < TT; s++) {
        float* Vr = (s & 1) ? Vbuf1 : Vbuf0;
        float* Vw = (s & 1) ? Vbuf0 : Vbuf1;

        // ---- VB = V * B  (12x4) ----
        float VB[NN][MM];
        #pragma unroll
        for (int i = 0; i < NN; i++)
            #pragma unroll
            for (int m = 0; m < MM; m++) VB[i][m] = 0.0f;
        #pragma unroll
        for (int j = 0; j < NN; j++) {
            float bj0 = sB[j*MM+0], bj1 = sB[j*MM+1], bj2 = sB[j*MM+2], bj3 = sB[j*MM+3];
            #pragma unroll
            for (int i = 0; i < NN; i++) {
                float vij = Vr[symidx(i, j) * BK];
                VB[i][0] += vij * bj0;
                VB[i][1] += vij * bj1;
                VB[i][2] += vij * bj2;
                VB[i][3] += vij * bj3;
            }
        }

        // ---- Quu = diag(Qu) + B^T VB ; qu = pu + B^T v ----
        float Quu[MM][MM];
        float qu[MM];
        #pragma unroll
        for (int m = 0; m < MM; m++) {
            qu[m] = pu[m];
            #pragma unroll
            for (int n2 = m; n2 < MM; n2++) Quu[m][n2] = (m == n2) ? Qu[m] : 0.0f;
        }
        #pragma unroll
        for (int i = 0; i < NN; i++) {
            float bi0 = sB[i*MM+0], bi1 = sB[i*MM+1], bi2 = sB[i*MM+2], bi3 = sB[i*MM+3];
            qu[0] += bi0 * v[i]; qu[1] += bi1 * v[i];
            qu[2] += bi2 * v[i]; qu[3] += bi3 * v[i];
            Quu[0][0] += bi0 * VB[i][0]; Quu[0][1] += bi0 * VB[i][1];
            Quu[0][2] += bi0 * VB[i][2]; Quu[0][3] += bi0 * VB[i][3];
            Quu[1][1] += bi1 * VB[i][1]; Quu[1][2] += bi1 * VB[i][2];
            Quu[1][3] += bi1 * VB[i][3];
            Quu[2][2] += bi2 * VB[i][2]; Quu[2][3] += bi2 * VB[i][3];
            Quu[3][3] += bi3 * VB[i][3];
        }
        Quu[1][0] = Quu[0][1]; Quu[2][0] = Quu[0][2]; Quu[3][0] = Quu[0][3];
        Quu[2][1] = Quu[1][2]; Quu[3][1] = Quu[1][3]; Quu[3][2] = Quu[2][3];

        // ---- M = A^T VB  (Qxu, 12x4) ----
        float Mx[NN][MM];
        #pragma unroll
        for (int n = 0; n < NN; n++)
            #pragma unroll
            for (int m = 0; m < MM; m++) Mx[n][m] = 0.0f;
        #pragma unroll
        for (int i = 0; i < NN; i++) {
            #pragma unroll
            for (int n = 0; n < NN; n++) {
                float ain = sA[i*NN+n];
                Mx[n][0] += ain * VB[i][0];
                Mx[n][1] += ain * VB[i][1];
                Mx[n][2] += ain * VB[i][2];
                Mx[n][3] += ain * VB[i][3];
            }
        }

        // ---- Cholesky of Quu (SPD) ----
        float l00 = sqrtf(Quu[0][0]);           float i00 = 1.0f / l00;
        float L10 = Quu[1][0] * i00;
        float L20 = Quu[2][0] * i00;
        float L30 = Quu[3][0] * i00;
        float l11 = sqrtf(Quu[1][1] - L10*L10); float i11 = 1.0f / l11;
        float L21 = (Quu[2][1] - L20*L10) * i11;
        float L31 = (Quu[3][1] - L30*L10) * i11;
        float l22 = sqrtf(Quu[2][2] - L20*L20 - L21*L21); float i22 = 1.0f / l22;
        float L32 = (Quu[3][2] - L30*L20 - L31*L21) * i22;
        float l33 = sqrtf(Quu[3][3] - L30*L30 - L31*L31 - L32*L32); float i33 = 1.0f / l33;

        // ---- K = -Quu^{-1} Qux  (Qux[:,n] = Mx[n][:]) ; kff = -Quu^{-1} qu ----
        float K[MM][NN], kff[MM];
        #pragma unroll
        for (int n = 0; n < NN; n++) {
            float y0 = Mx[n][0] * i00;
            float y1 = (Mx[n][1] - L10*y0) * i11;
            float y2 = (Mx[n][2] - L20*y0 - L21*y1) * i22;
            float y3 = (Mx[n][3] - L30*y0 - L31*y1 - L32*y2) * i33;
            float z3 = y3 * i33;
            float z2 = (y2 - L32*z3) * i22;
            float z1 = (y1 - L21*z2 - L31*z3) * i11;
            float z0 = (y0 - L10*z1 - L20*z2 - L30*z3) * i00;
            K[0][n] = -z0; K[1][n] = -z1; K[2][n] = -z2; K[3][n] = -z3;
        }
        {
            float y0 = qu[0] * i00;
            float y1 = (qu[1] - L10*y0) * i11;
            float y2 = (qu[2] - L20*y0 - L21*y1) * i22;
            float y3 = (qu[3] - L30*y0 - L31*y1 - L32*y2) * i33;
            float z3 = y3 * i33;
            float z2 = (y2 - L32*z3) * i22;
            float z1 = (y1 - L21*z2 - L31*z3) * i11;
            float z0 = (y0 - L10*z1 - L20*z2 - L30*z3) * i00;
            kff[0] = -z0; kff[1] = -z1; kff[2] = -z2; kff[3] = -z3;
        }

        // ---- store gains, coalesced across b ----
        {
            int base = (s * 52) * NBATCH + b;
            #pragma unroll
            for (int m = 0; m < MM; m++)
                #pragma unroll
                for (int n = 0; n < NN; n++)
                    g_gains[base + (m*NN + n) * NBATCH] = K[m][n];
            #pragma unroll
            for (int m = 0; m < MM; m++)
                g_gains[base + (48 + m) * NBATCH] = kff[m];
        }

        // ---- Vn = diag(Qx) + A^T V A + M K + (M K)^T + K^T Quu K  (upper tri) ----
        #pragma unroll
        for (int blk = 0; blk < 3; blk++) {
            const int c0 = blk * 4;
            // P[:,cc] = V * A[:, c0+cc]
            float P[NN][4];
            #pragma unroll
            for (int i = 0; i < NN; i++)
                #pragma unroll
                for (int cc = 0; cc < 4; cc++) P[i][cc] = 0.0f;
            #pragma unroll
            for (int j = 0; j < NN; j++) {
                float a0 = sA[j*NN + c0+0], a1 = sA[j*NN + c0+1];
                float a2 = sA[j*NN + c0+2], a3 = sA[j*NN + c0+3];
                #pragma unroll
                for (int i = 0; i < NN; i++) {
                    float vij = Vr[symidx(i, j) * BK];
                    P[i][0] += vij * a0;
                    P[i][1] += vij * a1;
                    P[i][2] += vij * a2;
                    P[i][3] += vij * a3;
                }
            }
            // tq[m][cc] = (Quu K)[m][c0+cc]
            float tq[MM][4];
            #pragma unroll
            for (int m = 0; m < MM; m++)
                #pragma unroll
                for (int cc = 0; cc < 4; cc++) {
                    float acc = 0.0f;
                    #pragma unroll
                    for (int pI = 0; pI < MM; pI++) acc += Quu[m][pI] * K[pI][c0+cc];
                    tq[m][cc] = acc;
                }
            #pragma unroll
            for (int r = 0; r < NN; r++) {
                if (r > c0 + 3) continue;   // folds at compile time
                float ar[NN];
                #pragma unroll
                for (int i = 0; i < NN; i++) ar[i] = sA[i*NN + r];
                #pragma unroll
                for (int cc = 0; cc < 4; cc++) {
                    const int c = c0 + cc;
                    if (r <= c) {
                        float val = (r == c) ? Qx[r] : 0.0f;
                        #pragma unroll
                        for (int i = 0; i < NN; i++) val += ar[i] * P[i][cc];
                        #pragma unroll
                        for (int m = 0; m < MM; m++)
                            val += Mx[r][m] * K[m][c] + Mx[c][m] * K[m][r];
                        #pragma unroll
                        for (int m = 0; m < MM; m++) val += K[m][r] * tq[m][cc];
                        Vw[symidx(r, c) * BK] = val;
                    }
                }
            }
        }

        // ---- vn = px + A^T v + M kff + K^T (qu + Quu kff) ----
        float tk[MM];
        #pragma unroll
        for (int m = 0; m < MM; m++) {
            float acc = 0.0f;
            #pragma unroll
            for (int pI = 0; pI < MM; pI++) acc += Quu[m][pI] * kff[pI];
            tk[m] = acc + qu[m];
        }
        float vn[NN];
        #pragma unroll
        for (int n = 0; n < NN; n++) vn[n] = px[n];
        #pragma unroll
        for (int i = 0; i < NN; i++) {
            float vi = v[i];
            #pragma unroll
            for (int n = 0; n < NN; n++) vn[n] += sA[i*NN + n] * vi;
        }
        #pragma unroll
        for (int n = 0; n < NN; n++) {
            float acc = vn[n];
            #pragma unroll
            for (int m = 0; m < MM; m++) acc += Mx[n][m] * kff[m] + K[m][n] * tk[m];
            v[n] = acc;
        }
    }
}

// ---------- forward pass: quad-split (4 lanes per batch), SMEM partial exchange ----------
__global__ void __launch_bounds__(BKF) fwd_kernel(
    const float* __restrict__ x_init, const float* __restrict__ Ag,
    const float* __restrict__ Bg, float* __restrict__ out)
{
    __shared__ float sm[192];
    __shared__ float sU[(BKF / 4) * 16];   // partial u: [quadInBlock*16 + c*4 + m]
    const int tid = threadIdx.x;
    for (int e = tid; e < 192; e += BKF) sm[e] = (e < 144) ? Ag[e] : Bg[e - 144];
    __syncthreads();
    const float* sA = sm;
    const float* sB = sm + 144;

    const int c  = tid & 3;        // lane-in-quad: owns x/K columns 3c..3c+2
    const int q  = tid >> 2;       // quad within block (0..31)
    const int b  = blockIdx.x * (BKF / 4) + q;
    const int n0 = 3 * c;

    float x[NN];                   // fully replicated per lane
    #pragma unroll
    for (int i = 0; i < NN; i++) x[i] = x_init[b * NN + i];

    #pragma unroll 1
    for (int t = 0; t < TT; t++) {
        const int s = TT - 1 - t;             // gains stored in backward order
        const int base = (s * 52) * NBATCH + b;

        // lane's K slice: K[m][n0+j], and kff[c]
        float Kl[MM][3];
        #pragma unroll
        for (int m = 0; m < MM; m++)
            #pragma unroll
            for (int j = 0; j < 3; j++)
                Kl[m][j] = g_gains[base + (m * NN + n0 + j) * NBATCH];
        const float kfc = g_gains[base + (48 + c) * NBATCH];

        // partial u[m] over owned x components (+ kff[c] folded into m==c slot)
        #pragma unroll
        for (int m = 0; m < MM; m++) {
            float acc = (m == c) ? kfc : 0.0f;
            #pragma unroll
            for (int j = 0; j < 3; j++) acc += Kl[m][j] * x[n0 + j];
            sU[q * 16 + c * 4 + m] = acc;
        }
        __syncthreads();

        float u[MM];
        #pragma unroll
        for (int m = 0; m < MM; m++)
            u[m] = sU[q * 16 + 0 * 4 + m] + sU[q * 16 + 1 * 4 + m]
                 + sU[q * 16 + 2 * 4 + m] + sU[q * 16 + 3 * 4 + m];
        __syncthreads();   // partials consumed before next step overwrites

        // x update, fully replicated (identical across lanes)
        float xn[NN];
        #pragma unroll
        for (int i = 0; i < NN; i++) {
            float acc = 0.0f;
            #pragma unroll
            for (int j = 0; j < NN; j++) acc += sA[i*NN + j] * x[j];
            #pragma unroll
            for (int m = 0; m < MM; m++) acc += sB[i*MM + m] * u[m];
            xn[i] = acc;
        }
        #pragma unroll
        for (int i = 0; i < NN; i++) x[i] = xn[i];

        // lane c stores u[c]: (b,c) consecutive -> 128B coalesced per warp
        float uc = u[0];
        if (c == 1) uc = u[1];
        if (c == 2) uc = u[2];
        if (c == 3) uc = u[3];
        out[((size_t)t * NBATCH + b) * MM + c] = uc;
    }
}

extern "C" void kernel_launch(void* const* d_in, const int* in_sizes, int n_in,
                              void* d_out, int out_size) {
    const float* x_init = (const float*)d_in[0];
    const float* Q      = (const float*)d_in[1];
    const float* p      = (const float*)d_in[2];
    const float* A      = (const float*)d_in[3];
    const float* B      = (const float*)d_in[4];
    float* out = (float*)d_out;

    bwd_kernel<<<NBATCH / BK, BK>>>(Q, p, A, B);                 // 128 x 64 (verified)
    fwd_kernel<<<(NBATCH * 4) / BKF, BKF>>>(x_init, A, B, out);  // 256 x 128, quad-split
}

// round 13
// speedup vs baseline: 2.0272x; 1.5790x over previous
#include <cuda_runtime.h>

#define TT 50
#define NN 12
#define MM 4
#define NBATCH 8192
#define BK 64             // bwd block: 16 quads
#define NQUAD 16
#define NSYM 78
#define XST 49            // sX per-thread stride (bank-conflict-free)
#define BKF 128           // fwd block: 32 quads

// Gains: [step s][entry e 0..51][batch b] (48 K + 4 kff) -- verified layout
__device__ float g_gains[TT * 52 * NBATCH];

__device__ __forceinline__ int symidx(int i, int j) {
    int a = i < j ? i : j;
    int c = i < j ? j : i;
    return a * NN - (a * (a + 1)) / 2 + c;
}

__global__ void __launch_bounds__(BK) bwd_kernel(
    const float* __restrict__ Qg, const float* __restrict__ pg,
    const float* __restrict__ Ag, const float* __restrict__ Bg)
{
    __shared__ float sA[144];          // A[i*12+j]
    __shared__ float sB[48];           // B[i*4+m]
    __shared__ float sV[NSYM * BK];    // thread-PRIVATE packed V (replicated per quad)
    __shared__ float sX[BK * XST];     // exchange scratch: thread t owns sX[t*XST .. +47]

    const int tid = threadIdx.x;
    for (int e = tid; e < 192; e += BK) {
        if (e < 144) sA[e] = Ag[e]; else sB[e - 144] = Bg[e - 144];
    }
    __syncthreads();

    const int c  = tid & 3;            // lane-in-quad, owns cols n0..n0+2
    const int q  = tid >> 2;           // quad in block
    const int b  = blockIdx.x * NQUAD + q;
    const int n0 = 3 * c;
    float* sVp = sV + tid;             // packed entry e at sVp[e*BK]

    // per-batch constants (replicated per lane)
    float Qx[NN], px[NN], Qu[MM], pu[MM];
    #pragma unroll
    for (int i = 0; i < NN; i++) { Qx[i] = Qg[b * 16 + i]; px[i] = pg[b * 16 + i]; }
    #pragma unroll
    for (int m = 0; m < MM; m++) { Qu[m] = Qg[b * 16 + 12 + m]; pu[m] = pg[b * 16 + 12 + m]; }

    // V = 0 (private), v = 0
    #pragma unroll
    for (int e = 0; e < NSYM; e++) sVp[e * BK] = 0.0f;
    float v[NN];
    #pragma unroll
    for (int i = 0; i < NN; i++) v[i] = 0.0f;

    #pragma unroll 1
    for (int s = 0; s < TT; s++) {
        // ===== Phase 1: VB partials over own j-chunk, exchange, reduce =====
        {
            float VBp[NN][MM];
            #pragma unroll
            for (int i = 0; i < NN; i++)
                #pragma unroll
                for (int m = 0; m < MM; m++) VBp[i][m] = 0.0f;
            #pragma unroll
            for (int jj = 0; jj < 3; jj++) {
                const int j = n0 + jj;
                const float b0 = sB[j*4+0], b1 = sB[j*4+1], b2 = sB[j*4+2], b3 = sB[j*4+3];
                #pragma unroll
                for (int i = 0; i < NN; i++) {
                    const float vij = sVp[symidx(i, j) * BK];
                    VBp[i][0] += vij * b0;
                    VBp[i][1] += vij * b1;
                    VBp[i][2] += vij * b2;
                    VBp[i][3] += vij * b3;
                }
            }
            #pragma unroll
            for (int i = 0; i < NN; i++)
                #pragma unroll
                for (int m = 0; m < MM; m++)
                    sX[tid * XST + i * 4 + m] = VBp[i][m];
        }
        __syncthreads();
        float VB[NN][MM];
        #pragma unroll
        for (int i = 0; i < NN; i++)
            #pragma unroll
            for (int m = 0; m < MM; m++)
                VB[i][m] = sX[(q*4+0) * XST + i*4+m] + sX[(q*4+1) * XST + i*4+m]
                         + sX[(q*4+2) * XST + i*4+m] + sX[(q*4+3) * XST + i*4+m];
        __syncthreads();   // sX free for reuse

        // ===== Replicated scalar block (R5-verbatim Z-form) =====
        float Quu[MM][MM];
        float qu[MM];
        #pragma unroll
        for (int m = 0; m < MM; m++) {
            qu[m] = pu[m];
            #pragma unroll
            for (int n2 = m; n2 < MM; n2++) Quu[m][n2] = (m == n2) ? Qu[m] : 0.0f;
        }
        #pragma unroll
        for (int i = 0; i < NN; i++) {
            float bi0 = sB[i*4+0], bi1 = sB[i*4+1], bi2 = sB[i*4+2], bi3 = sB[i*4+3];
            qu[0] += bi0 * v[i]; qu[1] += bi1 * v[i];
            qu[2] += bi2 * v[i]; qu[3] += bi3 * v[i];
            Quu[0][0] += bi0 * VB[i][0]; Quu[0][1] += bi0 * VB[i][1];
            Quu[0][2] += bi0 * VB[i][2]; Quu[0][3] += bi0 * VB[i][3];
            Quu[1][1] += bi1 * VB[i][1]; Quu[1][2] += bi1 * VB[i][2];
            Quu[1][3] += bi1 * VB[i][3];
            Quu[2][2] += bi2 * VB[i][2]; Quu[2][3] += bi2 * VB[i][3];
            Quu[3][3] += bi3 * VB[i][3];
        }

        float Mx[NN][MM];
        #pragma unroll
        for (int n = 0; n < NN; n++)
            #pragma unroll
            for (int m = 0; m < MM; m++) Mx[n][m] = 0.0f;
        #pragma unroll
        for (int i = 0; i < NN; i++) {
            #pragma unroll
            for (int n = 0; n < NN; n++) {
                const float ain = sA[i*NN+n];
                Mx[n][0] += ain * VB[i][0];
                Mx[n][1] += ain * VB[i][1];
                Mx[n][2] += ain * VB[i][2];
                Mx[n][3] += ain * VB[i][3];
            }
        }

        const float l00 = sqrtf(Quu[0][0]);                     const float i00 = 1.0f / l00;
        const float L10 = Quu[0][1] * i00;
        const float L20 = Quu[0][2] * i00;
        const float L30 = Quu[0][3] * i00;
        const float l11 = sqrtf(Quu[1][1] - L10*L10);           const float i11 = 1.0f / l11;
        const float L21 = (Quu[1][2] - L20*L10) * i11;
        const float L31 = (Quu[1][3] - L30*L10) * i11;
        const float l22 = sqrtf(Quu[2][2] - L20*L20 - L21*L21); const float i22 = 1.0f / l22;
        const float L32 = (Quu[2][3] - L30*L20 - L31*L21) * i22;
        const float l33 = sqrtf(Quu[3][3] - L30*L30 - L31*L31 - L32*L32);
        const float i33 = 1.0f / l33;

        float Zt[NN][MM];
        #pragma unroll
        for (int n = 0; n < NN; n++) {
            const float y0 = Mx[n][0] * i00;
            const float y1 = (Mx[n][1] - L10*y0) * i11;
            const float y2 = (Mx[n][2] - L20*y0 - L21*y1) * i22;
            const float y3 = (Mx[n][3] - L30*y0 - L31*y1 - L32*y2) * i33;
            Zt[n][0] = y0; Zt[n][1] = y1; Zt[n][2] = y2; Zt[n][3] = y3;
        }
        const float zq0 = qu[0] * i00;
        const float zq1 = (qu[1] - L10*zq0) * i11;
        const float zq2 = (qu[2] - L20*zq0 - L21*zq1) * i22;
        const float zq3 = (qu[3] - L30*zq0 - L31*zq1 - L32*zq2) * i33;

        // ===== gains: own cols (lane c -> n0..n0+2) + kff[c] =====
        {
            float Zo[3][MM];
            #pragma unroll
            for (int k = 0; k < 3; k++)
                #pragma unroll
                for (int m = 0; m < MM; m++) {
                    float z = Zt[k][m];
                    if (c == 1) z = Zt[3 + k][m];
                    if (c == 2) z = Zt[6 + k][m];
                    if (c == 3) z = Zt[9 + k][m];
                    Zo[k][m] = z;
                }
            const int base = (s * 52) * NBATCH + b;
            #pragma unroll
            for (int k = 0; k < 3; k++) {
                const float w3 = Zo[k][3] * i33;
                const float w2 = (Zo[k][2] - L32*w3) * i22;
                const float w1 = (Zo[k][1] - L21*w2 - L31*w3) * i11;
                const float w0 = (Zo[k][0] - L10*w1 - L20*w2 - L30*w3) * i00;
                const int n = n0 + k;
                g_gains[base + (0*NN + n) * NBATCH] = -w0;
                g_gains[base + (1*NN + n) * NBATCH] = -w1;
                g_gains[base + (2*NN + n) * NBATCH] = -w2;
                g_gains[base + (3*NN + n) * NBATCH] = -w3;
            }
            const float w3 = zq3 * i33;
            const float w2 = (zq2 - L32*w3) * i22;
            const float w1 = (zq1 - L21*w2 - L31*w3) * i11;
            const float w0 = (zq0 - L10*w1 - L20*w2 - L30*w3) * i00;
            float kfc = -w0;
            if (c == 1) kfc = -w1;
            if (c == 2) kfc = -w2;
            if (c == 3) kfc = -w3;
            g_gains[base + (48 + c) * NBATCH] = kfc;
        }

        // ===== vn = px + A^T v - Zt zq (replicated, R5-verbatim) =====
        {
            float vn[NN];
            #pragma unroll
            for (int n = 0; n < NN; n++)
                vn[n] = px[n] - (Zt[n][0]*zq0 + Zt[n][1]*zq1 + Zt[n][2]*zq2 + Zt[n][3]*zq3);
            #pragma unroll
            for (int i = 0; i < NN; i++) {
                const float vi = v[i];
                #pragma unroll
                for (int n = 0; n < NN; n++) vn[n] += sA[i*NN + n] * vi;
            }
            #pragma unroll
            for (int n = 0; n < NN; n++) v[n] = vn[n];
        }

        // ===== Phase 3: W = V*A own cols (private V reads, no comm) =====
        float W[NN][3];
        #pragma unroll
        for (int i = 0; i < NN; i++)
            #pragma unroll
            for (int k = 0; k < 3; k++) W[i][k] = 0.0f;
        #pragma unroll
        for (int j = 0; j < NN; j++) {
            const float a0 = sA[j*12 + n0 + 0];
            const float a1 = sA[j*12 + n0 + 1];
            const float a2 = sA[j*12 + n0 + 2];
            #pragma unroll
            for (int i = 0; i < NN; i++) {
                const float vij = sVp[symidx(i, j) * BK];
                W[i][0] += vij * a0;
                W[i][1] += vij * a1;
                W[i][2] += vij * a2;
            }
        }
        // ===== Phase 4: S = A^T W own cols (complete), exchange =====
        {
            float S[NN][3];
            #pragma unroll
            for (int r = 0; r < NN; r++)
                #pragma unroll
                for (int k = 0; k < 3; k++) S[r][k] = 0.0f;
            #pragma unroll
            for (int i = 0; i < NN; i++) {
                #pragma unroll
                for (int r = 0; r < NN; r++) {
                    const float a = sA[i*12 + r];
                    S[r][0] += a * W[i][0];
                    S[r][1] += a * W[i][1];
                    S[r][2] += a * W[i][2];
                }
            }
            #pragma unroll
            for (int r = 0; r < NN; r++)
                #pragma unroll
                for (int k = 0; k < 3; k++)
                    sX[tid * XST + r * 3 + k] = S[r][k];
        }
        __syncthreads();

        // ===== Phase 5: Vn assembly (replicated), write private V =====
        #pragma unroll
        for (int r = 0; r < NN; r++) {
            #pragma unroll
            for (int cc = r; cc < NN; cc++) {
                const int owner = cc / 3;        // compile-time
                const int kk = cc % 3;           // compile-time
                float val = (r == cc) ? Qx[r] : 0.0f;
                val += sX[(q * 4 + owner) * XST + r * 3 + kk];   // S[r][cc]
                val -= Zt[r][0]*Zt[cc][0] + Zt[r][1]*Zt[cc][1]
                     + Zt[r][2]*Zt[cc][2] + Zt[r][3]*Zt[cc][3];
                sVp[symidx(r, cc) * BK] = val;
            }
        }
        __syncthreads();   // S consumed by all lanes before next-step sX writes
    }
}

// ---------- forward pass: R12-verified quad-split, verbatim ----------
__global__ void __launch_bounds__(BKF) fwd_kernel(
    const float* __restrict__ x_init, const float* __restrict__ Ag,
    const float* __restrict__ Bg, float* __restrict__ out)
{
    __shared__ float sm[192];
    __shared__ float sU[(BKF / 4) * 16];
    const int tid = threadIdx.x;
    for (int e = tid; e < 192; e += BKF) sm[e] = (e < 144) ? Ag[e] : Bg[e - 144];
    __syncthreads();
    const float* sA = sm;
    const float* sB = sm + 144;

    const int c  = tid & 3;
    const int q  = tid >> 2;
    const int b  = blockIdx.x * (BKF / 4) + q;
    const int n0 = 3 * c;

    float x[NN];
    #pragma unroll
    for (int i = 0; i < NN; i++) x[i] = x_init[b * NN + i];

    #pragma unroll 1
    for (int t = 0; t < TT; t++) {
        const int s = TT - 1 - t;
        const int base = (s * 52) * NBATCH + b;

        float Kl[MM][3];
        #pragma unroll
        for (int m = 0; m < MM; m++)
            #pragma unroll
            for (int j = 0; j < 3; j++)
                Kl[m][j] = g_gains[base + (m * NN + n0 + j) * NBATCH];
        const float kfc = g_gains[base + (48 + c) * NBATCH];

        #pragma unroll
        for (int m = 0; m < MM; m++) {
            float acc = (m == c) ? kfc : 0.0f;
            #pragma unroll
            for (int j = 0; j < 3; j++) acc += Kl[m][j] * x[n0 + j];
            sU[q * 16 + c * 4 + m] = acc;
        }
        __syncthreads();

        float u[MM];
        #pragma unroll
        for (int m = 0; m < MM; m++)
            u[m] = sU[q * 16 + 0 * 4 + m] + sU[q * 16 + 1 * 4 + m]
                 + sU[q * 16 + 2 * 4 + m] + sU[q * 16 + 3 * 4 + m];
        __syncthreads();

        float xn[NN];
        #pragma unroll
        for (int i = 0; i < NN; i++) {
            float acc = 0.0f;
            #pragma unroll
            for (int j = 0; j < NN; j++) acc += sA[i*NN + j] * x[j];
            #pragma unroll
            for (int m = 0; m < MM; m++) acc += sB[i*MM + m] * u[m];
            xn[i] = acc;
        }
        #pragma unroll
        for (int i = 0; i < NN; i++) x[i] = xn[i];

        float uc = u[0];
        if (c == 1) uc = u[1];
        if (c == 2) uc = u[2];
        if (c == 3) uc = u[3];
        out[((size_t)t * NBATCH + b) * MM + c] = uc;
    }
}

extern "C" void kernel_launch(void* const* d_in, const int* in_sizes, int n_in,
                              void* d_out, int out_size) {
    const float* x_init = (const float*)d_in[0];
    const float* Q      = (const float*)d_in[1];
    const float* p      = (const float*)d_in[2];
    const float* A      = (const float*)d_in[3];
    const float* B      = (const float*)d_in[4];
    float* out = (float*)d_out;

    bwd_kernel<<<NBATCH / NQUAD, BK>>>(Q, p, A, B);              // 512 x 64, quad-coop
    fwd_kernel<<<(NBATCH * 4) / BKF, BKF>>>(x_init, A, B, out);  // 256 x 128 (verified)
}

// round 17
// speedup vs baseline: 2.6018x; 1.2834x over previous
#include <cuda_runtime.h>

#define TT 50
#define NN 12
#define MM 4
#define NBATCH 8192
#define BK 64             // bwd block: 16 quads
#define NQUAD 16
#define NSYM 78
#define XST 49            // sX per-thread stride (conflict-free scalar exchange)
#define BKF 128           // fwd block: 32 quads

// Gains: [step s][entry e 0..51][batch b] (48 K + 4 kff) -- verified layout
__device__ float g_gains[TT * 52 * NBATCH];

__device__ __forceinline__ int symidx(int i, int j) {
    int a = i < j ? i : j;
    int c = i < j ? j : i;
    return a * NN - (a * (a + 1)) / 2 + c;
}

__global__ void __launch_bounds__(BK) bwd_kernel(
    const float* __restrict__ Qg, const float* __restrict__ pg,
    const float* __restrict__ Ag, const float* __restrict__ Bg)
{
    __shared__ float sA[144];            // A[i*12+j]
    __shared__ float sB[48];             // B[i*4+m]
    __shared__ float sV[NSYM * BK];      // thread-PRIVATE packed V (replicated per quad)
    __shared__ float sX[2][BK * XST];    // double-buffered exchange scratch

    const int tid = threadIdx.x;
    for (int e = tid; e < 192; e += BK) {
        if (e < 144) sA[e] = Ag[e]; else sB[e - 144] = Bg[e - 144];
    }
    __syncthreads();

    const int c  = tid & 3;              // lane-in-quad, owns cols/rows n0..n0+2
    const int q  = tid >> 2;
    const int b  = blockIdx.x * NQUAD + q;
    const int n0 = 3 * c;
    float* sVp = sV + tid;

    // per-batch constants: own slices + full Qu/pu
    float Qxo[3], pxo[3], Qu[MM], pu[MM];
    #pragma unroll
    for (int k = 0; k < 3; k++) { Qxo[k] = Qg[b * 16 + n0 + k]; pxo[k] = pg[b * 16 + n0 + k]; }
    #pragma unroll
    for (int m = 0; m < MM; m++) { Qu[m] = Qg[b * 16 + 12 + m]; pu[m] = pg[b * 16 + 12 + m]; }

    // V = 0 (private), v = 0 (replicated)
    #pragma unroll
    for (int e = 0; e < NSYM; e++) sVp[e * BK] = 0.0f;
    float v[NN];
    #pragma unroll
    for (int i = 0; i < NN; i++) v[i] = 0.0f;

    int xb = 0;   // exchange buffer parity

    #pragma unroll 1
    for (int s = 0; s < TT; s++) {
        // ===== Exchange 1: VB partials over own j-chunk (R13-verbatim pattern) =====
        {
            float* Xw = sX[xb];
            float VBp[NN][MM];
            #pragma unroll
            for (int i = 0; i < NN; i++)
                #pragma unroll
                for (int m = 0; m < MM; m++) VBp[i][m] = 0.0f;
            #pragma unroll
            for (int jj = 0; jj < 3; jj++) {
                const int j = n0 + jj;
                const float b0 = sB[j*4+0], b1 = sB[j*4+1], b2 = sB[j*4+2], b3 = sB[j*4+3];
                #pragma unroll
                for (int i = 0; i < NN; i++) {
                    const float vij = sVp[symidx(i, j) * BK];
                    VBp[i][0] += vij * b0;
                    VBp[i][1] += vij * b1;
                    VBp[i][2] += vij * b2;
                    VBp[i][3] += vij * b3;
                }
            }
            #pragma unroll
            for (int i = 0; i < NN; i++)
                #pragma unroll
                for (int m = 0; m < MM; m++)
                    Xw[tid * XST + i * 4 + m] = VBp[i][m];
        }
        __syncthreads();
        float VB[NN][MM];
        {
            float* Xr = sX[xb];
            #pragma unroll
            for (int i = 0; i < NN; i++)
                #pragma unroll
                for (int m = 0; m < MM; m++)
                    VB[i][m] = Xr[(q*4+0) * XST + i*4+m] + Xr[(q*4+1) * XST + i*4+m]
                             + Xr[(q*4+2) * XST + i*4+m] + Xr[(q*4+3) * XST + i*4+m];
        }
        xb ^= 1;

        // ===== Quu/qu (replicated; R13-verbatim) =====
        float Quu[MM][MM];
        float qu[MM];
        #pragma unroll
        for (int m = 0; m < MM; m++) {
            qu[m] = pu[m];
            #pragma unroll
            for (int n2 = m; n2 < MM; n2++) Quu[m][n2] = (m == n2) ? Qu[m] : 0.0f;
        }
        #pragma unroll
        for (int i = 0; i < NN; i++) {
            float bi0 = sB[i*4+0], bi1 = sB[i*4+1], bi2 = sB[i*4+2], bi3 = sB[i*4+3];
            qu[0] += bi0 * v[i]; qu[1] += bi1 * v[i];
            qu[2] += bi2 * v[i]; qu[3] += bi3 * v[i];
            Quu[0][0] += bi0 * VB[i][0]; Quu[0][1] += bi0 * VB[i][1];
            Quu[0][2] += bi0 * VB[i][2]; Quu[0][3] += bi0 * VB[i][3];
            Quu[1][1] += bi1 * VB[i][1]; Quu[1][2] += bi1 * VB[i][2];
            Quu[1][3] += bi1 * VB[i][3];
            Quu[2][2] += bi2 * VB[i][2]; Quu[2][3] += bi2 * VB[i][3];
            Quu[3][3] += bi3 * VB[i][3];
        }

        // ===== Mo = own rows of Qux (A^T VB, rows n0..n0+2) =====
        float Mo[3][MM];
        #pragma unroll
        for (int k = 0; k < 3; k++)
            #pragma unroll
            for (int m = 0; m < MM; m++) Mo[k][m] = 0.0f;
        #pragma unroll
        for (int i = 0; i < NN; i++) {
            #pragma unroll
            for (int k = 0; k < 3; k++) {
                const float a = sA[i*12 + n0 + k];
                Mo[k][0] += a * VB[i][0];
                Mo[k][1] += a * VB[i][1];
                Mo[k][2] += a * VB[i][2];
                Mo[k][3] += a * VB[i][3];
            }
        }

        // ===== Cholesky (replicated; R13-verbatim) =====
        const float l00 = sqrtf(Quu[0][0]);                     const float i00 = 1.0f / l00;
        const float L10 = Quu[0][1] * i00;
        const float L20 = Quu[0][2] * i00;
        const float L30 = Quu[0][3] * i00;
        const float l11 = sqrtf(Quu[1][1] - L10*L10);           const float i11 = 1.0f / l11;
        const float L21 = (Quu[1][2] - L20*L10) * i11;
        const float L31 = (Quu[1][3] - L30*L10) * i11;
        const float l22 = sqrtf(Quu[2][2] - L20*L20 - L21*L21); const float i22 = 1.0f / l22;
        const float L32 = (Quu[2][3] - L30*L20 - L31*L21) * i22;
        const float l33 = sqrtf(Quu[3][3] - L30*L30 - L31*L31 - L32*L32);
        const float i33 = 1.0f / l33;

        // ===== Zo = L^{-1} Mo^T (own rows of Zt) =====
        float Zo[3][MM];
        #pragma unroll
        for (int k = 0; k < 3; k++) {
            const float y0 = Mo[k][0] * i00;
            const float y1 = (Mo[k][1] - L10*y0) * i11;
            const float y2 = (Mo[k][2] - L20*y0 - L21*y1) * i22;
            const float y3 = (Mo[k][3] - L30*y0 - L31*y1 - L32*y2) * i33;
            Zo[k][0] = y0; Zo[k][1] = y1; Zo[k][2] = y2; Zo[k][3] = y3;
        }
        const float zq0 = qu[0] * i00;
        const float zq1 = (qu[1] - L10*zq0) * i11;
        const float zq2 = (qu[2] - L20*zq0 - L21*zq1) * i22;
        const float zq3 = (qu[3] - L30*zq0 - L31*zq1 - L32*zq2) * i33;

        // ===== gains: own cols + kff[c] (layout verified by R12/R13 fwd) =====
        {
            const int base = (s * 52) * NBATCH + b;
            #pragma unroll
            for (int k = 0; k < 3; k++) {
                const float w3 = Zo[k][3] * i33;
                const float w2 = (Zo[k][2] - L32*w3) * i22;
                const float w1 = (Zo[k][1] - L21*w2 - L31*w3) * i11;
                const float w0 = (Zo[k][0] - L10*w1 - L20*w2 - L30*w3) * i00;
                const int n = n0 + k;
                g_gains[base + (0*NN + n) * NBATCH] = -w0;
                g_gains[base + (1*NN + n) * NBATCH] = -w1;
                g_gains[base + (2*NN + n) * NBATCH] = -w2;
                g_gains[base + (3*NN + n) * NBATCH] = -w3;
            }
            const float w3 = zq3 * i33;
            const float w2 = (zq2 - L32*w3) * i22;
            const float w1 = (zq1 - L21*w2 - L31*w3) * i11;
            const float w0 = (zq0 - L10*w1 - L20*w2 - L30*w3) * i00;
            float kfc = -w0;
            if (c == 1) kfc = -w1;
            if (c == 2) kfc = -w2;
            if (c == 3) kfc = -w3;
            g_gains[base + (48 + c) * NBATCH] = kfc;
        }

        // ===== Exchange 2: Zo rows -> full Zt =====
        {
            float* Xw = sX[xb];
            #pragma unroll
            for (int k = 0; k < 3; k++)
                #pragma unroll
                for (int m = 0; m < MM; m++)
                    Xw[tid * XST + k * 4 + m] = Zo[k][m];
        }
        __syncthreads();
        float Zt[NN][MM];
        {
            float* Xr = sX[xb];
            #pragma unroll
            for (int n = 0; n < NN; n++) {
                const int owner = n / 3, kk = n % 3;    // compile-time
                #pragma unroll
                for (int m = 0; m < MM; m++)
                    Zt[n][m] = Xr[(q * 4 + owner) * XST + kk * 4 + m];
            }
        }
        xb ^= 1;

        // ===== vn own rows: vno[k] = px[n0+k] + (A^T v)[n0+k] - Zo[k]·zq =====
        float vno[3];
        #pragma unroll
        for (int k = 0; k < 3; k++) {
            float acc = pxo[k] - (Zo[k][0]*zq0 + Zo[k][1]*zq1 + Zo[k][2]*zq2 + Zo[k][3]*zq3);
            #pragma unroll
            for (int i = 0; i < NN; i++) acc += sA[i*12 + n0 + k] * v[i];
            vno[k] = acc;
        }

        // ===== W = V*A own cols; S = A^T W own cols (R13-verbatim) =====
        float W[NN][3];
        #pragma unroll
        for (int i = 0; i < NN; i++)
            #pragma unroll
            for (int k = 0; k < 3; k++) W[i][k] = 0.0f;
        #pragma unroll
        for (int j = 0; j < NN; j++) {
            const float a0 = sA[j*12 + n0 + 0];
            const float a1 = sA[j*12 + n0 + 1];
            const float a2 = sA[j*12 + n0 + 2];
            #pragma unroll
            for (int i = 0; i < NN; i++) {
                const float vij = sVp[symidx(i, j) * BK];
                W[i][0] += vij * a0;
                W[i][1] += vij * a1;
                W[i][2] += vij * a2;
            }
        }
        float S[NN][3];
        #pragma unroll
        for (int r = 0; r < NN; r++)
            #pragma unroll
            for (int k = 0; k < 3; k++) S[r][k] = 0.0f;
        #pragma unroll
        for (int i = 0; i < NN; i++) {
            #pragma unroll
            for (int r = 0; r < NN; r++) {
                const float a = sA[i*12 + r];
                S[r][0] += a * W[i][0];
                S[r][1] += a * W[i][1];
                S[r][2] += a * W[i][2];
            }
        }

        // ===== Exchange 3: Vn own cols (from register S/Zo) + vno =====
        {
            float* Xw = sX[xb];
            #pragma unroll
            for (int r = 0; r < NN; r++) {
                #pragma unroll
                for (int k = 0; k < 3; k++) {
                    float val = S[r][k]
                        - (Zt[r][0]*Zo[k][0] + Zt[r][1]*Zo[k][1]
                         + Zt[r][2]*Zo[k][2] + Zt[r][3]*Zo[k][3]);
                    if (r == n0 + k) val += Qxo[k];
                    Xw[tid * XST + r * 3 + k] = val;
                }
            }
            #pragma unroll
            for (int k = 0; k < 3; k++)
                Xw[tid * XST + 36 + k] = vno[k];
        }
        __syncthreads();
        {
            float* Xr = sX[xb];
            // private packed V from owners (upper-tri entries)
            #pragma unroll
            for (int r = 0; r < NN; r++) {
                #pragma unroll
                for (int cc = r; cc < NN; cc++) {
                    const int owner = cc / 3, kk = cc % 3;   // compile-time
                    sVp[symidx(r, cc) * BK] = Xr[(q * 4 + owner) * XST + r * 3 + kk];
                }
            }
            // full v from owners
            #pragma unroll
            for (int n = 0; n < NN; n++) {
                const int owner = n / 3, kk = n % 3;
                v[n] = Xr[(q * 4 + owner) * XST + 36 + kk];
            }
        }
        xb ^= 1;
        // NOTE: next iteration's first write targets the other buffer; reads above
        // complete before this thread reaches the next __syncthreads (safe).
    }
}

// ---------- forward pass: R12-verified quad-split + gains prefetch + 1 barrier ----------
__global__ void __launch_bounds__(BKF) fwd_kernel(
    const float* __restrict__ x_init, const float* __restrict__ Ag,
    const float* __restrict__ Bg, float* __restrict__ out)
{
    __shared__ float sm[192];
    __shared__ float sU[2][(BKF / 4) * 16];
    const int tid = threadIdx.x;
    for (int e = tid; e < 192; e += BKF) sm[e] = (e < 144) ? Ag[e] : Bg[e - 144];
    __syncthreads();
    const float* sA = sm;
    const float* sB = sm + 144;

    const int c  = tid & 3;
    const int q  = tid >> 2;
    const int b  = blockIdx.x * (BKF / 4) + q;
    const int n0 = 3 * c;

    float x[NN];
    #pragma unroll
    for (int i = 0; i < NN; i++) x[i] = x_init[b * NN + i];

    // preload gains for t = 0 (s = TT-1)
    float Kl[MM][3], kfc;
    {
        const int base = ((TT - 1) * 52) * NBATCH + b;
        #pragma unroll
        for (int m = 0; m < MM; m++)
            #pragma unroll
            for (int j = 0; j < 3; j++)
                Kl[m][j] = g_gains[base + (m * NN + n0 + j) * NBATCH];
        kfc = g_gains[base + (48 + c) * NBATCH];
    }

    #pragma unroll 1
    for (int t = 0; t < TT; t++) {
        const int s = TT - 1 - t;
        // prefetch next step's gains (clamped; redundant load on last iter)
        const int sn = (s > 0) ? (s - 1) : 0;
        const int basen = (sn * 52) * NBATCH + b;
        float Kl2[MM][3], kfc2;
        #pragma unroll
        for (int m = 0; m < MM; m++)
            #pragma unroll
            for (int j = 0; j < 3; j++)
                Kl2[m][j] = g_gains[basen + (m * NN + n0 + j) * NBATCH];
        kfc2 = g_gains[basen + (48 + c) * NBATCH];

        const int pb = t & 1;
        #pragma unroll
        for (int m = 0; m < MM; m++) {
            float acc = (m == c) ? kfc : 0.0f;
            #pragma unroll
            for (int j = 0; j < 3; j++) acc += Kl[m][j] * x[n0 + j];
            sU[pb][q * 16 + c * 4 + m] = acc;
        }
        __syncthreads();

        float u[MM];
        #pragma unroll
        for (int m = 0; m < MM; m++)
            u[m] = sU[pb][q * 16 + 0 * 4 + m] + sU[pb][q * 16 + 1 * 4 + m]
                 + sU[pb][q * 16 + 2 * 4 + m] + sU[pb][q * 16 + 3 * 4 + m];

        float xn[NN];
        #pragma unroll
        for (int i = 0; i < NN; i++) {
            float acc = 0.0f;
            #pragma unroll
            for (int j = 0; j < NN; j++) acc += sA[i*NN + j] * x[j];
            #pragma unroll
            for (int m = 0; m < MM; m++) acc += sB[i*MM + m] * u[m];
            xn[i] = acc;
        }
        #pragma unroll
        for (int i = 0; i < NN; i++) x[i] = xn[i];

        float uc = u[0];
        if (c == 1) uc = u[1];
        if (c == 2) uc = u[2];
        if (c == 3) uc = u[3];
        out[((size_t)t * NBATCH + b) * MM + c] = uc;

        #pragma unroll
        for (int m = 0; m < MM; m++)
            #pragma unroll
            for (int j = 0; j < 3; j++) Kl[m][j] = Kl2[m][j];
        kfc = kfc2;
    }
}

extern "C" void kernel_launch(void* const* d_in, const int* in_sizes, int n_in,
                              void* d_out, int out_size) {
    const float* x_init = (const float*)d_in[0];
    const float* Q      = (const float*)d_in[1];
    const float* p      = (const float*)d_in[2];
    const float* A      = (const float*)d_in[3];
    const float* B      = (const float*)d_in[4];
    float* out = (float*)d_out;

    bwd_kernel<<<NBATCH / NQUAD, BK>>>(Q, p, A, B);              // 512 x 64, quad-coop v2
    fwd_kernel<<<(NBATCH * 4) / BKF, BKF>>>(x_init, A, B, out);  // 256 x 128, prefetch
}